// round 4
// baseline (speedup 1.0000x reference)
#include <cuda_runtime.h>
#include <cuda_bf16.h>
#include <cstdint>

#define NN   128   // nodes
#define DD   128   // dim
#define EE   128   // edge types
#define NG   8     // graphs
#define VDIM 300

// ---------------- device scratch (allocation-free) ----------------
__device__ float g_base[NN * DD];
__device__ float g_vpos[NG][DD];
__device__ float g_u[NG][NN][DD];    // u[path_idx][k], idx>=1 used
__device__ float g_w2[NG][DD];
__device__ float g_cconst[NG];
__device__ float g_dscore;

// tree-structure scratch (filled by k_parse)
__device__ int g_par[NG][NN];
__device__ int g_cc[NG][NN];
__device__ int g_ord[NG][NN];
__device__ int g_lvlstart[NG][NN + 2];
__device__ int g_maxh[NG];
__device__ int g_plen[NG];
__device__ int g_plist[NG][NN];
__device__ int g_pedge[NG][NN];

// =============== tree parse: 1 thread per graph ===============
__global__ void k_parse(const int* __restrict__ graphs,
                        const int* __restrict__ edges,
                        const int* __restrict__ posp) {
    int g = blockIdx.x;
    int pos = *posp;
    const int* go = graphs + g * NN;
    int par[NN], h[NN], roots[NN];
    unsigned char inpath[NN];
    int nr = 0;
    for (int i = 0; i < NN; i++) {
        int off = go[i];
        if (off == 0) { roots[nr++] = i; par[i] = -1; }
        else { int p = i + off; par[i] = (p < NN) ? p : -1; }
    }
    // faithful root chaining: parents[roots[i]] = roots[i+1] stored as OFFSET
    for (int i = 0; i < nr - 1; i++) {
        int p = roots[i] + roots[i + 1];   // i + (roots[i+1]) offset semantics
        par[roots[i]] = (p < NN) ? p : -1;
    }
    int root = roots[nr - 1];
    par[root] = -1;
    for (int i = 0; i < NN; i++) { h[i] = 0; inpath[i] = 0; g_cc[g][i] = 0; }
    for (int i = 0; i < NN; i++) { int p = par[i]; if (p >= 0) g_cc[g][p]++; }
    // parent index > child index (offsets positive) -> ascending pass = heights
    for (int i = 0; i < NN; i++) {
        int p = par[i];
        if (p >= 0 && h[i] + 1 > h[p]) h[p] = h[i] + 1;
    }
    // path pos -> root
    int plen = 0, p = pos;
    while (p >= 0) {
        inpath[p] = 1;
        g_plist[g][plen] = p;
        g_pedge[g][plen] = edges[p];
        plen++;
        p = par[p];
    }
    g_plen[g] = plen;
    // counting sort of non-path nodes by height
    int cnt[NN + 1];
    for (int l = 0; l <= NN; l++) cnt[l] = 0;
    int maxh = 0;
    for (int i = 0; i < NN; i++)
        if (!inpath[i]) { cnt[h[i]]++; if (h[i] > maxh) maxh = h[i]; }
    g_maxh[g] = maxh;
    int run = 0;
    for (int l = 0; l <= maxh + 1; l++) {
        g_lvlstart[g][l] = run;
        if (l <= maxh) run += cnt[l];
    }
    int cur[NN + 1];
    for (int l = 0; l <= maxh; l++) cur[l] = g_lvlstart[g][l];
    for (int i = 0; i < NN; i++)
        if (!inpath[i]) g_ord[g][cur[h[i]]++] = i;
    for (int i = 0; i < NN; i++) g_par[g][i] = par[i];
}

// =============== base[n,k] = data_vecs[data[n]] @ dw + db ===============
__global__ void k_base(const int* __restrict__ data,
                       const float* __restrict__ dv,
                       const float* __restrict__ dw,
                       const float* __restrict__ db) {
    int n = blockIdx.x, k = threadIdx.x;
    const float* vr = dv + (size_t)data[n] * VDIM;
    float acc = db[k];
#pragma unroll 5
    for (int v = 0; v < VDIM; v++) acc += vr[v] * dw[v * DD + k];
    g_base[n * DD + k] = acc;
}

// =============== d_score = sb + base[pos] . sdw ===============
__global__ void k_dscore(const int* __restrict__ posp,
                         const float* __restrict__ sdw,
                         const float* __restrict__ sb) {
    __shared__ float red[DD];
    int t = threadIdx.x;
    int pos = *posp;
    red[t] = g_base[pos * DD + t] * sdw[t];
    __syncthreads();
    for (int s = 64; s > 0; s >>= 1) {
        if (t < s) red[t] += red[t + s];
        __syncthreads();
    }
    if (t == 0) g_dscore = red[0] + sb[0];
}

// =============== vector pass: one CTA per graph ===============
__global__ void __launch_bounds__(1024, 1)
k_vec(const int* __restrict__ edges,
      const float* __restrict__ ew,
      const float* __restrict__ eb) {
    extern __shared__ float s_vacc[];              // NN*DD floats = 64KB
    __shared__ int s_par[NN], s_cc[NN], s_ord[NN];
    __shared__ int s_lvlstart[NN + 2];

    int g = blockIdx.x, tid = threadIdx.x;

    // init vacc = base; copy tree metadata to smem
    for (int i = tid; i < NN * DD; i += blockDim.x) s_vacc[i] = g_base[i];
    if (tid < NN) {
        s_par[tid] = g_par[g][tid];
        s_cc[tid]  = g_cc[g][tid];
        s_ord[tid] = g_ord[g][tid];
    }
    if (tid < NN + 2) s_lvlstart[tid] = g_lvlstart[g][tid];
    __syncthreads();

    int maxh = g_maxh[g];
    int warp = tid >> 5, lane = tid & 31;
    int k0 = lane * 4;
    int nwarps = blockDim.x >> 5;

    for (int L = 0; L <= maxh; L++) {
        int st = s_lvlstart[L], en = s_lvlstart[L + 1];
        int units = (en - st) << 2;                 // 4 k-chunks per node
        for (int u = warp; u < units; u += nwarps) {
            int node = s_ord[st + (u >> 2)];
            int chunk = u & 3;
            int p = s_par[node];
            if (p < 0) continue;                    // detached subtree
            int e = edges[node];
            bool hasch = (s_cc[node] > 0);
            const float* W = ew + (size_t)e * (DD * DD);
            float y0, y1, y2, y3;
            if (chunk == 0) {
                const float* b = eb + e * DD;
                y0 = b[k0]; y1 = b[k0 + 1]; y2 = b[k0 + 2]; y3 = b[k0 + 3];
            } else { y0 = y1 = y2 = y3 = 0.f; }
            int d0 = chunk * 32;
#pragma unroll 8
            for (int d = d0; d < d0 + 32; d++) {
                float v = s_vacc[node * DD + d];
                if (hasch) v = fmaxf(v, 0.f);
                float4 w = *(const float4*)(W + d * DD + k0);
                y0 += v * w.x; y1 += v * w.y; y2 += v * w.z; y3 += v * w.w;
            }
            float* dst = &s_vacc[p * DD + k0];
            atomicAdd(dst + 0, y0); atomicAdd(dst + 1, y1);
            atomicAdd(dst + 2, y2); atomicAdd(dst + 3, y3);
        }
        __syncthreads();
    }

    // export v_pos and u[] for path nodes
    int plen = g_plen[g];
    if (tid < DD) {
        int p0 = g_plist[g][0];
        float v = s_vacc[p0 * DD + tid];
        if (s_cc[p0] > 0) v = fmaxf(v, 0.f);
        g_vpos[g][tid] = v;
        for (int idx = 1; idx < plen; idx++)
            g_u[g][idx][tid] = s_vacc[g_plist[g][idx] * DD + tid];
    }
}

// =============== fold root transform into score vector ===============
__global__ void k_fold(const float* __restrict__ ew,
                       const float* __restrict__ eb,
                       const float* __restrict__ sw) {
    __shared__ float ss[DD];
    __shared__ float red[DD];
    int g = blockIdx.x, t = threadIdx.x;
    int er = g_pedge[g][g_plen[g] - 1];
    ss[t] = sw[t];
    __syncthreads();
    const float* W = ew + (size_t)er * (DD * DD);
    float acc = 0.f;
#pragma unroll 4
    for (int k = 0; k < DD; k++) acc += W[t * DD + k] * ss[k];
    g_w2[g][t] = acc;
    red[t] = eb[er * DD + t] * ss[t];
    __syncthreads();
    for (int s = 64; s > 0; s >>= 1) {
        if (t < s) red[t] += red[t + s];
        __syncthreads();
    }
    if (t == 0) g_cconst[g] = red[0];
}

// =============== path pass: 1 warp per (graph, e) chain ===============
__global__ void __launch_bounds__(512)
k_chain(const float* __restrict__ ew,
        const float* __restrict__ eb,
        const float* __restrict__ sw,
        float* __restrict__ out) {
    __shared__ float s_m[16][DD];
    __shared__ float s_v0[DD];
    int g = blockIdx.x >> 3, ec = blockIdx.x & 7;
    int warp = threadIdx.x >> 5, lane = threadIdx.x & 31;
    int e = ec * 16 + warp;
    if (threadIdx.x < DD) s_v0[threadIdx.x] = g_vpos[g][threadIdx.x];
    __syncthreads();

    int plen = g_plen[g];
    int k0 = lane * 4;

    // step 0: y = v0 @ W[e] + b[e]  (the unknown-edge node branches over all e)
    const float* W = ew + (size_t)e * (DD * DD);
    const float* b = eb + e * DD;
    float y0 = b[k0], y1 = b[k0 + 1], y2 = b[k0 + 2], y3 = b[k0 + 3];
#pragma unroll 8
    for (int d = 0; d < DD; d++) {
        float v = s_v0[d];
        float4 w = *(const float4*)(W + d * DD + k0);
        y0 += v * w.x; y1 += v * w.y; y2 += v * w.z; y3 += v * w.w;
    }

    float sc;
    bool deg = (plen == 1);   // pos == root: res = perE(v0) then dot raw s
    if (deg) {
        sc = y0 * sw[k0] + y1 * sw[k0 + 1] + y2 * sw[k0 + 2] + y3 * sw[k0 + 3];
    } else {
        const float* u1 = &g_u[g][1][0];
        float m0 = fmaxf(u1[k0] + y0, 0.f);
        float m1 = fmaxf(u1[k0 + 1] + y1, 0.f);
        float m2 = fmaxf(u1[k0 + 2] + y2, 0.f);
        float m3 = fmaxf(u1[k0 + 3] + y3, 0.f);
        for (int i = 2; i < plen; i++) {
            s_m[warp][k0] = m0; s_m[warp][k0 + 1] = m1;
            s_m[warp][k0 + 2] = m2; s_m[warp][k0 + 3] = m3;
            __syncwarp();
            int eid = g_pedge[g][i - 1];
            const float* Wi = ew + (size_t)eid * (DD * DD);
            const float* bi = eb + eid * DD;
            float t0 = bi[k0], t1 = bi[k0 + 1], t2 = bi[k0 + 2], t3 = bi[k0 + 3];
#pragma unroll 8
            for (int d = 0; d < DD; d++) {
                float v = s_m[warp][d];
                float4 w = *(const float4*)(Wi + d * DD + k0);
                t0 += v * w.x; t1 += v * w.y; t2 += v * w.z; t3 += v * w.w;
            }
            __syncwarp();
            const float* ui = &g_u[g][i][0];
            m0 = fmaxf(ui[k0] + t0, 0.f);
            m1 = fmaxf(ui[k0 + 1] + t1, 0.f);
            m2 = fmaxf(ui[k0 + 2] + t2, 0.f);
            m3 = fmaxf(ui[k0 + 3] + t3, 0.f);
        }
        const float* w2 = &g_w2[g][0];
        sc = m0 * w2[k0] + m1 * w2[k0 + 1] + m2 * w2[k0 + 2] + m3 * w2[k0 + 3];
    }
    // warp reduce
    for (int off = 16; off; off >>= 1) sc += __shfl_xor_sync(0xFFFFFFFFu, sc, off);
    if (lane == 0) {
        float r = g_dscore + sc;
        if (!deg) r += g_cconst[g];
        out[g * EE + e] = r;
    }
}

// =============== launcher ===============
extern "C" void kernel_launch(void* const* d_in, const int* in_sizes, int n_in,
                              void* d_out, int out_size) {
    const int*   data   = (const int*)d_in[0];
    // d_in[1] = types (unused: single data_type)
    const int*   graphs = (const int*)d_in[2];
    const int*   edges  = (const int*)d_in[3];
    const int*   pos    = (const int*)d_in[4];
    const float* dv     = (const float*)d_in[5];
    const float* dw     = (const float*)d_in[6];
    const float* db     = (const float*)d_in[7];
    const float* ew     = (const float*)d_in[8];
    const float* ebias  = (const float*)d_in[9];
    const float* sew    = (const float*)d_in[10];
    const float* sdw    = (const float*)d_in[11];
    const float* sb     = (const float*)d_in[12];
    float* out = (float*)d_out;

    static bool attr_done = false;
    if (!attr_done) {
        cudaFuncSetAttribute(k_vec, cudaFuncAttributeMaxDynamicSharedMemorySize, NN * DD * 4);
        attr_done = true;
    }

    k_parse <<<NG, 1>>>(graphs, edges, pos);
    k_base  <<<NN, DD>>>(data, dv, dw, db);
    k_dscore<<<1, DD>>>(pos, sdw, sb);
    k_vec   <<<NG, 1024, NN * DD * 4>>>(edges, ew, ebias);
    k_fold  <<<NG, DD>>>(ew, ebias, sew);
    k_chain <<<NG * 8, 512>>>(ew, ebias, sew, out);
}